// round 1
// baseline (speedup 1.0000x reference)
#include <cuda_runtime.h>
#include <math.h>

#define Bc    4
#define Tt    2048
#define TRAIN 1536
#define Dd    512
#define Hh    8
#define DHd   64
#define Ll    12
#define FFd   2048
#define Vv    100
#define BT    (Bc*Tt)
#define TEST  (Tt-TRAIN)
#define MTEST (Bc*TEST)

// ---------------- scratch (static device globals; no allocations) ----------------
__device__ float g_rep [BT*Dd];          // residual stream
__device__ float g_h   [BT*Dd];          // LN output
__device__ float g_qkv [BT*3*Dd];        // fused qkv
__device__ float g_attn[BT*Dd];          // attention output
__device__ float g_ff  [BT*FFd];         // FF hidden
__device__ float g_test[MTEST*Dd];       // head input
__device__ float g_phid[MTEST*2*Dd];     // head hidden
__device__ float g_cos [Tt*32];
__device__ float g_sin [Tt*32];

// ---------------- helpers ----------------
__device__ __forceinline__ float gelu_f(float x){
    float x3 = x*x*x;
    return 0.5f*x*(1.f + tanhf(0.7978845608028654f*(x + 0.044715f*x3)));
}

// ---------------- embedding add ----------------
__global__ void embed_kernel(const float* __restrict__ R, const int* __restrict__ y,
                             const float* __restrict__ emb){
    int row = blockIdx.x;           // b*T + t
    int t = row & (Tt-1);
    int b = row >> 11;
    const float4* Rr = (const float4*)(R + (size_t)row*Dd);
    float4* Or = (float4*)(g_rep + (size_t)row*Dd);
    if (t < TRAIN){
        int yv = y[b*TRAIN + t];
        const float4* E = (const float4*)(emb + (size_t)yv*Dd);
        for (int i = threadIdx.x; i < Dd/4; i += blockDim.x){
            float4 a = Rr[i]; float4 e = E[i];
            a.x += e.x; a.y += e.y; a.z += e.z; a.w += e.w;
            Or[i] = a;
        }
    } else {
        for (int i = threadIdx.x; i < Dd/4; i += blockDim.x) Or[i] = Rr[i];
    }
}

// ---------------- layernorm (one block per row, 128 threads) ----------------
__global__ void ln_kernel(const float* __restrict__ x, const float* __restrict__ g,
                          const float* __restrict__ be, float* __restrict__ out){
    __shared__ float sh[Dd];
    __shared__ float red[4];
    int row = blockIdx.x;
    const float* xr = x + (size_t)row*Dd;
    float s = 0.f;
    for (int i = threadIdx.x; i < Dd; i += 128){ float v = xr[i]; sh[i] = v; s += v; }
    #pragma unroll
    for (int o = 16; o; o >>= 1) s += __shfl_xor_sync(0xffffffffu, s, o);
    if ((threadIdx.x & 31) == 0) red[threadIdx.x >> 5] = s;
    __syncthreads();
    float mu = (red[0]+red[1]+red[2]+red[3]) * (1.f/Dd);
    float vs = 0.f;
    for (int i = threadIdx.x; i < Dd; i += 128){ float d = sh[i]-mu; vs += d*d; }
    #pragma unroll
    for (int o = 16; o; o >>= 1) vs += __shfl_xor_sync(0xffffffffu, vs, o);
    __syncthreads();
    if ((threadIdx.x & 31) == 0) red[threadIdx.x >> 5] = vs;
    __syncthreads();
    float var = (red[0]+red[1]+red[2]+red[3]) * (1.f/Dd);
    float rs = rsqrtf(var + 1e-5f);
    float* orow = out + (size_t)row*Dd;
    for (int i = threadIdx.x; i < Dd; i += 128)
        orow[i] = (sh[i]-mu)*rs*g[i] + be[i];
}

// ---------------- RoPE table (matches JAX fp32 op sequence) ----------------
__global__ void rope_table_kernel(){
    int t = blockIdx.x, i = threadIdx.x;   // i in 0..31
    float inv = (float)pow(100000.0, -((double)(2*i))/64.0);
    float ang = (float)t * inv;
    g_cos[t*32+i] = cosf(ang);
    g_sin[t*32+i] = sinf(ang);
}

// ---------------- RoPE apply (interleaved) on q and k in g_qkv ----------------
__global__ void rope_apply_kernel(){
    int row = blockIdx.x;              // b*T + t
    int t = row & (Tt-1);
    int h = threadIdx.x >> 5;          // 0..7
    int i = threadIdx.x & 31;          // 0..31
    float c = g_cos[t*32+i], s = g_sin[t*32+i];
    size_t base = (size_t)row*(3*Dd) + h*DHd + 2*i;
    float q1 = g_qkv[base], q2 = g_qkv[base+1];
    g_qkv[base]   = q1*c - q2*s;
    g_qkv[base+1] = q1*s + q2*c;
    size_t kb = base + Dd;
    float k1 = g_qkv[kb], k2 = g_qkv[kb+1];
    g_qkv[kb]   = k1*c - k2*s;
    g_qkv[kb+1] = k1*s + k2*c;
}

// ---------------- flash attention ----------------
// mask: allowed = (s < TRAIN) || (s == t). So: loop keys 0..TRAIN-1, then one
// self-key fixup for t >= TRAIN. Online softmax, fp32 throughout.
// grid: (T/16, H, B), block 256 = 8 warps, each warp handles 2 query rows.
__global__ __launch_bounds__(256) void attn_kernel(){
    const int b = blockIdx.z, h = blockIdx.y;
    const int t0 = blockIdx.x * 16;
    const int warp = threadIdx.x >> 5, lane = threadIdx.x & 31;
    const float SCALE = 0.125f; // 1/sqrt(64)

    __shared__ float Qs[16][64];
    __shared__ float Ks[64][65];
    __shared__ float Vs[64][65];
    __shared__ float Ps[16][64];

    const size_t rstride = 3*Dd;
    // load 16 query rows
    for (int idx = threadIdx.x; idx < 16*64; idx += 256){
        int r = idx >> 6, d = idx & 63;
        Qs[r][d] = g_qkv[(size_t)(b*Tt + t0 + r)*rstride + h*DHd + d];
    }
    __syncthreads();

    float m[2]  = {-INFINITY, -INFINITY};
    float lsum[2] = {0.f, 0.f};
    float o[2][2] = {{0.f,0.f},{0.f,0.f}};    // dims: lane, lane+32

    for (int s0 = 0; s0 < TRAIN; s0 += 64){
        for (int idx = threadIdx.x; idx < 64*64; idx += 256){
            int s = idx >> 6, d = idx & 63;
            size_t base = (size_t)(b*Tt + s0 + s)*rstride + h*DHd + d;
            Ks[s][d] = g_qkv[base + Dd];
            Vs[s][d] = g_qkv[base + 2*Dd];
        }
        __syncthreads();
        #pragma unroll
        for (int r = 0; r < 2; r++){
            int row = warp*2 + r;
            float sc0 = 0.f, sc1 = 0.f;
            #pragma unroll 16
            for (int d = 0; d < 64; d++){
                float q = Qs[row][d];
                sc0 += q * Ks[lane][d];
                sc1 += q * Ks[lane+32][d];
            }
            sc0 *= SCALE; sc1 *= SCALE;
            float tmax = fmaxf(sc0, sc1);
            #pragma unroll
            for (int off = 16; off; off >>= 1)
                tmax = fmaxf(tmax, __shfl_xor_sync(0xffffffffu, tmax, off));
            float mnew = fmaxf(m[r], tmax);
            float alpha = expf(m[r] - mnew);
            float p0 = expf(sc0 - mnew), p1 = expf(sc1 - mnew);
            float psum = p0 + p1;
            #pragma unroll
            for (int off = 16; off; off >>= 1)
                psum += __shfl_xor_sync(0xffffffffu, psum, off);
            lsum[r] = lsum[r]*alpha + psum;
            o[r][0] *= alpha; o[r][1] *= alpha;
            m[r] = mnew;
            Ps[row][lane] = p0; Ps[row][lane+32] = p1;
            __syncwarp();
            #pragma unroll 16
            for (int kk = 0; kk < 64; kk++){
                float p = Ps[row][kk];
                o[r][0] += p * Vs[kk][lane];
                o[r][1] += p * Vs[kk][lane+32];
            }
            __syncwarp();
        }
        __syncthreads();
    }

    // self-key fixup + writeback
    #pragma unroll
    for (int r = 0; r < 2; r++){
        int row = warp*2 + r;
        int t = t0 + row;
        if (t >= TRAIN){
            size_t base = (size_t)(b*Tt + t)*rstride + h*DHd;
            float part = Qs[row][lane]    * g_qkv[base + Dd + lane]
                       + Qs[row][lane+32] * g_qkv[base + Dd + lane + 32];
            #pragma unroll
            for (int off = 16; off; off >>= 1)
                part += __shfl_xor_sync(0xffffffffu, part, off);
            float sv = part * SCALE;
            float mnew = fmaxf(m[r], sv);
            float alpha = expf(m[r] - mnew);
            float p = expf(sv - mnew);
            lsum[r] = lsum[r]*alpha + p;
            o[r][0] = o[r][0]*alpha + p * g_qkv[base + 2*Dd + lane];
            o[r][1] = o[r][1]*alpha + p * g_qkv[base + 2*Dd + lane + 32];
            m[r] = mnew;
        }
        float inv = 1.f / lsum[r];
        size_t orow = (size_t)(b*Tt + t)*Dd + h*DHd;
        g_attn[orow + lane]      = o[r][0]*inv;
        g_attn[orow + lane + 32] = o[r][1]*inv;
    }
}

// ---------------- tiled fp32 GEMM: C = epilogue(A[M,K] @ Bw[K,N] + bias) ----------------
// EPI: 0 = +bias, 1 = gelu(+bias), 2 = res + (+bias)
template<int EPI>
__global__ __launch_bounds__(256) void gemm_kernel(
    const float* __restrict__ A, const float* __restrict__ Bw,
    const float* __restrict__ bias, const float* res,
    float* C, int M, int N, int K)
{
    __shared__ __align__(16) float As[16][64];   // [k][m]
    __shared__ __align__(16) float Bs[16][64];   // [k][n]
    const int tid = threadIdx.x;
    const int m0 = blockIdx.y * 64, n0 = blockIdx.x * 64;
    const int ty = tid >> 4, tx = tid & 15;      // microtile coords

    const int arow = tid >> 2;                   // 0..63
    const int acol = (tid & 3) * 4;              // 0..12
    const int brow = tid >> 4;                   // 0..15
    const int bcol = (tid & 15) * 4;             // 0..60

    const float* Aptr = A + (size_t)(m0 + arow)*K + acol;
    float acc[4][4] = {};

    for (int k0 = 0; k0 < K; k0 += 16){
        float4 av = *(const float4*)(Aptr + k0);
        As[acol+0][arow] = av.x;
        As[acol+1][arow] = av.y;
        As[acol+2][arow] = av.z;
        As[acol+3][arow] = av.w;
        float4 bv;
        if (n0 + bcol < N)
            bv = *(const float4*)(Bw + (size_t)(k0 + brow)*N + n0 + bcol);
        else
            bv = make_float4(0.f,0.f,0.f,0.f);
        *(float4*)&Bs[brow][bcol] = bv;
        __syncthreads();
        #pragma unroll
        for (int kk = 0; kk < 16; kk++){
            float4 a = *(const float4*)&As[kk][ty*4];
            float4 bb = *(const float4*)&Bs[kk][tx*4];
            float ar[4] = {a.x, a.y, a.z, a.w};
            float br[4] = {bb.x, bb.y, bb.z, bb.w};
            #pragma unroll
            for (int i = 0; i < 4; i++)
                #pragma unroll
                for (int j = 0; j < 4; j++)
                    acc[i][j] += ar[i]*br[j];
        }
        __syncthreads();
    }

    #pragma unroll
    for (int i = 0; i < 4; i++){
        int mm = m0 + ty*4 + i;
        #pragma unroll
        for (int j = 0; j < 4; j++){
            int nn = n0 + tx*4 + j;
            if (nn < N){
                float v = acc[i][j] + bias[nn];
                if (EPI == 1) v = gelu_f(v);
                if (EPI == 2) v += res[(size_t)mm*N + nn];
                C[(size_t)mm*N + nn] = v;
            }
        }
    }
}

// ---------------- extract test rows ----------------
__global__ void extract_kernel(){
    int r = blockIdx.x;                  // 0..MTEST-1
    int b = r >> 9, i = r & 511;
    const float4* src = (const float4*)(g_rep + (size_t)(b*Tt + TRAIN + i)*Dd);
    float4* dst = (float4*)(g_test + (size_t)r*Dd);
    for (int j = threadIdx.x; j < Dd/4; j += blockDim.x) dst[j] = src[j];
}

// ---------------- launcher ----------------
extern "C" void kernel_launch(void* const* d_in, const int* in_sizes, int n_in,
                              void* d_out, int out_size){
    const float* R    = (const float*)d_in[0];
    const int*   y    = (const int*)  d_in[1];
    const float* emb  = (const float*)d_in[2];
    const float* Wqkv = (const float*)d_in[3];
    const float* bqkv = (const float*)d_in[4];
    const float* Wo   = (const float*)d_in[5];
    const float* bo   = (const float*)d_in[6];
    const float* ln1g = (const float*)d_in[7];
    const float* ln1b = (const float*)d_in[8];
    const float* ln2g = (const float*)d_in[9];
    const float* ln2b = (const float*)d_in[10];
    const float* W1   = (const float*)d_in[11];
    const float* b1   = (const float*)d_in[12];
    const float* W2   = (const float*)d_in[13];
    const float* b2   = (const float*)d_in[14];
    const float* pW1  = (const float*)d_in[15];
    const float* pb1  = (const float*)d_in[16];
    const float* pW2  = (const float*)d_in[17];
    const float* pb2  = (const float*)d_in[18];

    float *rep, *h, *qkv, *attn, *ff, *test, *phid;
    cudaGetSymbolAddress((void**)&rep,  g_rep);
    cudaGetSymbolAddress((void**)&h,    g_h);
    cudaGetSymbolAddress((void**)&qkv,  g_qkv);
    cudaGetSymbolAddress((void**)&attn, g_attn);
    cudaGetSymbolAddress((void**)&ff,   g_ff);
    cudaGetSymbolAddress((void**)&test, g_test);
    cudaGetSymbolAddress((void**)&phid, g_phid);

    rope_table_kernel<<<Tt, 32>>>();
    embed_kernel<<<BT, 128>>>(R, y, emb);

    for (int l = 0; l < Ll; l++){
        ln_kernel<<<BT, 128>>>(rep, ln1g + l*Dd, ln1b + l*Dd, h);
        gemm_kernel<0><<<dim3(24, 128), 256>>>(h, Wqkv + (size_t)l*Dd*3*Dd,
                                               bqkv + (size_t)l*3*Dd, nullptr, qkv,
                                               BT, 3*Dd, Dd);
        rope_apply_kernel<<<BT, 256>>>();
        attn_kernel<<<dim3(Tt/16, Hh, Bc), 256>>>();
        gemm_kernel<2><<<dim3(8, 128), 256>>>(attn, Wo + (size_t)l*Dd*Dd,
                                              bo + (size_t)l*Dd, rep, rep,
                                              BT, Dd, Dd);
        ln_kernel<<<BT, 128>>>(rep, ln2g + l*Dd, ln2b + l*Dd, h);
        gemm_kernel<1><<<dim3(32, 128), 256>>>(h, W1 + (size_t)l*Dd*FFd,
                                               b1 + (size_t)l*FFd, nullptr, ff,
                                               BT, FFd, Dd);
        gemm_kernel<2><<<dim3(8, 128), 256>>>(ff, W2 + (size_t)l*FFd*Dd,
                                              b2 + (size_t)l*Dd, rep, rep,
                                              BT, Dd, FFd);
    }

    extract_kernel<<<MTEST, 128>>>();
    gemm_kernel<1><<<dim3(16, MTEST/64), 256>>>(test, pW1, pb1, nullptr, phid,
                                                MTEST, 2*Dd, Dd);
    gemm_kernel<0><<<dim3(2, MTEST/64), 256>>>(phid, pW2, pb2, nullptr,
                                               (float*)d_out, MTEST, Vv, 2*Dd);
}